// round 8
// baseline (speedup 1.0000x reference)
#include <cuda_runtime.h>

#define NB 16
#define NC 64
#define HW 65536
#define NBINS 256
#define NBLK 512                 // 4 cohorts x 128 blocks, all co-resident
#define COH 128                  // blocks per cohort

// ---- scratch (no allocations allowed) ----
__device__ float         d_part[NB * NC * 2];
__device__ unsigned int  d_hist[NB * NBINS];
__device__ float         d_scale[NB * NBINS];
__device__ unsigned char d_q[NB * HW];
__device__ unsigned int  d_c1[NB];              // mean arrivals (==128 ready)
__device__ unsigned int  d_c2[NB];              // cos arrivals (==129 LUT ready)

__global__ void k_init() {
    d_hist[blockIdx.x * NBINS + threadIdx.x] = 0u;
    if (threadIdx.x == 0) { d_c1[blockIdx.x] = 0u; d_c2[blockIdx.x] = 0u; }
}

__device__ __forceinline__ void spin_ge(const unsigned int* p, unsigned int v) {
    const volatile unsigned int* vp = (const volatile unsigned int*)p;
    while (*vp < v) __nanosleep(64);
}

// out = F * scale[q], one batch slice (8192 float4 per block)
__device__ __forceinline__ void do_mul(const float* __restrict__ F,
                                       float* __restrict__ out,
                                       const float* sS, int b, int sub, int tid) {
    const float4* Fb = (const float4*)F + ((size_t)b << 20);
    float4*       Ob = (float4*)out + ((size_t)b << 20);
    const int base = sub << 13;
    #pragma unroll 4
    for (int k = 0; k < 32; ++k) {
        int idx = base + k * 256 + tid;
        int p4  = idx & 16383;
        uchar4 q = *(const uchar4*)(d_q + ((size_t)b << 16) + ((size_t)p4 << 2));
        float4 v = __ldcs(Fb + idx);            // last use: evict-first
        float4 o;
        o.x = v.x * sS[q.x];
        o.y = v.y * sS[q.y];
        o.z = v.z * sS[q.z];
        o.w = v.w * sS[q.w];
        __stcs(Ob + idx, o);                    // streaming store
    }
}

// ============================================================
// Persistent cohort kernel, software-pipelined:
//   iter i: mean(b_i) -> mul(b_{i-1}) -> wait -> cos/hist/LUT(b_i)
// ============================================================
__global__ void __launch_bounds__(256, 4) k_mega(const float* __restrict__ F,
                                                 float* __restrict__ out) {
    const int tid    = threadIdx.x;
    const int cohort = blockIdx.x >> 7;
    const int sub    = blockIdx.x & 127;

    __shared__ float        sPart[8 * 256];
    __shared__ float        sA[NBINS];          // a-hat
    __shared__ float        sS[NBINS];          // scale table (mul)
    __shared__ unsigned int sU[NBINS];
    __shared__ int          sLast;

    int prevb = -1;
    for (int i = 0; i < 4; ++i) {
        const int b = i * 4 + cohort;

        // ---------------- Phase 1: mean partials for batch b ----------------
        {
            const int c = sub >> 1, half = sub & 1;
            const float4* base = (const float4*)F +
                ((size_t)(b * NC + c) << 14) + ((size_t)half << 13);
            float s = 0.f;
            #pragma unroll 8
            for (int j = 0; j < 32; ++j) {
                float4 v = __ldcg(base + j * 256 + tid);
                s += (v.x + v.y) + (v.z + v.w);
            }
            sPart[tid] = s;
            __syncthreads();
            for (int o = 128; o > 0; o >>= 1) {
                if (tid < o) sPart[tid] += sPart[tid + o];
                __syncthreads();
            }
            if (tid == 0) {
                d_part[(b * NC + c) * 2 + half] = sPart[0];
                __threadfence();
                atomicAdd(&d_c1[b], 1u);
            }
            __syncthreads();
        }

        // -------- Deferred Phase 3: mul(prevb) — hides the means wait --------
        if (prevb >= 0) {
            if (tid == 0) spin_ge(&d_c2[prevb], COH + 1);
            __syncthreads();
            __threadfence();
            sS[tid] = d_scale[prevb * NBINS + tid];
            __syncthreads();
            do_mul(F, out, sS, prevb, sub, tid);
        }

        // ---------------- wait: all means of batch b ----------------
        if (tid == 0) spin_ge(&d_c1[b], COH);
        __syncthreads();
        __threadfence();

        // a-hat (fixed-order combine)
        if (tid < NC)
            sA[tid] = (d_part[(b * NC + tid) * 2] +
                       d_part[(b * NC + tid) * 2 + 1]) * (1.0f / HW);
        sU[tid] = 0u;
        __syncthreads();
        sPart[tid] = (tid < NC) ? sA[tid] * sA[tid] : 0.f;
        __syncthreads();
        for (int o = 128; o > 0; o >>= 1) {
            if (tid < o) sPart[tid] += sPart[tid + o];
            __syncthreads();
        }
        const float inv = 1.0f / fmaxf(sqrtf(sPart[0]), 1e-12f);
        __syncthreads();
        if (tid < NC) sA[tid] *= inv;
        __syncthreads();

        // ---------------- Phase 2: cosine + quantize + histogram ----------------
        {
            const int px = (sub << 7) + (tid & 127);
            const int c0 = (tid >> 7) << 5;
            const float4* fp = (const float4*)F + ((size_t)b << 20) + px;
            float d0 = 0.f, d1 = 0.f, d2 = 0.f, d3 = 0.f;
            float s0 = 0.f, s1 = 0.f, s2 = 0.f, s3 = 0.f;
            #pragma unroll 8
            for (int ci = 0; ci < 32; ++ci) {
                float4 v = fp[(size_t)(c0 + ci) << 14];
                float ac = sA[c0 + ci];
                d0 += ac * v.x; d1 += ac * v.y; d2 += ac * v.z; d3 += ac * v.w;
                s0 += v.x * v.x; s1 += v.y * v.y; s2 += v.z * v.z; s3 += v.w * v.w;
            }
            sPart[0 * 256 + tid] = d0; sPart[1 * 256 + tid] = d1;
            sPart[2 * 256 + tid] = d2; sPart[3 * 256 + tid] = d3;
            sPart[4 * 256 + tid] = s0; sPart[5 * 256 + tid] = s1;
            sPart[6 * 256 + tid] = s2; sPart[7 * 256 + tid] = s3;
            __syncthreads();

            if (tid < 128) {
                float D0 = sPart[0 * 256 + tid] + sPart[0 * 256 + tid + 128];
                float D1 = sPart[1 * 256 + tid] + sPart[1 * 256 + tid + 128];
                float D2 = sPart[2 * 256 + tid] + sPart[2 * 256 + tid + 128];
                float D3 = sPart[3 * 256 + tid] + sPart[3 * 256 + tid + 128];
                float S0 = sPart[4 * 256 + tid] + sPart[4 * 256 + tid + 128];
                float S1 = sPart[5 * 256 + tid] + sPart[5 * 256 + tid + 128];
                float S2 = sPart[6 * 256 + tid] + sPart[6 * 256 + tid + 128];
                float S3 = sPart[7 * 256 + tid] + sPart[7 * 256 + tid + 128];
                int q0 = ((int)((D0 / fmaxf(sqrtf(S0), 1e-12f)) * 255.0f)) & 255;
                int q1 = ((int)((D1 / fmaxf(sqrtf(S1), 1e-12f)) * 255.0f)) & 255;
                int q2 = ((int)((D2 / fmaxf(sqrtf(S2), 1e-12f)) * 255.0f)) & 255;
                int q3 = ((int)((D3 / fmaxf(sqrtf(S3), 1e-12f)) * 255.0f)) & 255;
                atomicAdd(&sU[q0], 1u); atomicAdd(&sU[q1], 1u);
                atomicAdd(&sU[q2], 1u); atomicAdd(&sU[q3], 1u);
                const int mypx = (sub << 7) + tid;
                *(uchar4*)(d_q + ((size_t)b << 16) + ((size_t)mypx << 2)) =
                    make_uchar4((unsigned char)q0, (unsigned char)q1,
                                (unsigned char)q2, (unsigned char)q3);
            }
            __syncthreads();
            unsigned int cnt = sU[tid];
            if (cnt) atomicAdd(&d_hist[b * NBINS + tid], cnt);
            __syncthreads();

            if (tid == 0) {
                __threadfence();
                unsigned int old = atomicAdd(&d_c2[b], 1u);
                sLast = (old == COH - 1);
            }
            __syncthreads();

            if (sLast) {                          // last cos block builds LUT
                __threadfence();
                float h = (float)d_hist[b * NBINS + tid];
                float* cdf = sPart;
                float* tmp = sPart + 256;
                cdf[tid] = h;
                __syncthreads();
                for (int o = 1; o < NBINS; o <<= 1) {
                    float v = cdf[tid];
                    float add = (tid >= o) ? cdf[tid - o] : 0.f;
                    __syncthreads();
                    cdf[tid] = v + add;
                    __syncthreads();
                }
                tmp[tid] = (h > 0.f) ? cdf[tid] : (float)(HW + 1);
                __syncthreads();
                for (int o = 128; o > 0; o >>= 1) {
                    if (tid < o) tmp[tid] = fminf(tmp[tid], tmp[tid + o]);
                    __syncthreads();
                }
                float cmin  = tmp[0];
                float denom = fmaxf((float)HW - cmin, 1.0f);
                float lut   = rintf((cdf[tid] - cmin) * (255.0f / denom));
                lut = fminf(fmaxf(lut, 0.0f), 255.0f);
                d_scale[b * NBINS + tid] = lut * (1.0f / 255.0f);
                __syncthreads();
                if (tid == 0) {
                    __threadfence();
                    atomicAdd(&d_c2[b], 1u);      // -> 129 : LUT ready
                }
            }
            __syncthreads();
        }
        prevb = b;
    }

    // ---------------- Epilogue: mul for the last batch ----------------
    if (tid == 0) spin_ge(&d_c2[prevb], COH + 1);
    __syncthreads();
    __threadfence();
    sS[tid] = d_scale[prevb * NBINS + tid];
    __syncthreads();
    do_mul(F, out, sS, prevb, sub, tid);
}

// ============================================================
extern "C" void kernel_launch(void* const* d_in, const int* in_sizes, int n_in,
                              void* d_out, int out_size) {
    const float* F = (const float*)d_in[0];
    float* out = (float*)d_out;
    (void)in_sizes; (void)n_in; (void)out_size;

    k_init<<<NB, NBINS>>>();
    k_mega<<<NBLK, 256>>>(F, out);
}

// round 9
// speedup vs baseline: 1.1053x; 1.1053x over previous
#include <cuda_runtime.h>

#define NB 16
#define NC 64
#define HW 65536
#define NBINS 256
#define NBLK 512
#define NA  128     // stage A (mean) blocks: 2 per plane
#define NBB 128     // stage B (cos/hist) blocks
#define NCC 256     // stage C (mul) blocks

// ---- scratch (no allocations allowed) ----
__device__ float         d_part[NB * NC * 2];   // per-(plane,half) partial sums
__device__ unsigned int  d_hist[NB * NBINS];
__device__ float         d_scale[NB * NBINS];
__device__ unsigned char d_q[NB * HW];
__device__ unsigned int  d_cA[NB];              // A arrivals (==128: means ready)
__device__ unsigned int  d_cB[NB];              // B arrivals (==129: LUT ready)
__device__ unsigned int  d_cC[NB];              // C arrivals (==256: batch written)

__global__ void k_init() {
    d_hist[blockIdx.x * NBINS + threadIdx.x] = 0u;
    if (threadIdx.x == 0) {
        d_cA[blockIdx.x] = 0u; d_cB[blockIdx.x] = 0u; d_cC[blockIdx.x] = 0u;
    }
}

__device__ __forceinline__ void spin_ge(const unsigned int* p, unsigned int v) {
    const volatile unsigned int* vp = (const volatile unsigned int*)p;
    while (*vp < v) __nanosleep(64);
}

// ============================================================
// Persistent 3-stage pipeline over batches.
//   A: DRAM read b+2 (fills L2)   B: L2 read b+1, cos/hist/LUT
//   C: L2 read b, DRAM write b
// ============================================================
__global__ void __launch_bounds__(256, 4) k_pipe(const float* __restrict__ F,
                                                 float* __restrict__ out) {
    const int tid = threadIdx.x;
    const int bid = blockIdx.x;

    __shared__ float        sPart[8 * 256];
    __shared__ float        sA[NBINS];
    __shared__ unsigned int sU[NBINS];
    __shared__ int          sLast;

    if (bid < NA) {
        // ================= Stage A: plane means (DRAM -> L2 fill) =============
        const int c = bid >> 1, half = bid & 1;
        for (int b = 0; b < NB; ++b) {
            if (b >= 3) {                        // keep <=4 slabs (64 MB) in L2
                if (tid == 0) spin_ge(&d_cC[b - 3], NCC);
                __syncthreads();
            }
            const float4* base = (const float4*)F +
                ((size_t)(b * NC + c) << 14) + ((size_t)half << 13);
            float s = 0.f;
            #pragma unroll 8
            for (int j = 0; j < 32; ++j) {
                float4 v = __ldcg(base + j * 256 + tid);   // fill L2, skip L1
                s += (v.x + v.y) + (v.z + v.w);
            }
            sPart[tid] = s;
            __syncthreads();
            for (int o = 128; o > 0; o >>= 1) {
                if (tid < o) sPart[tid] += sPart[tid + o];
                __syncthreads();
            }
            if (tid == 0) {
                d_part[(b * NC + c) * 2 + half] = sPart[0];
                __threadfence();
                atomicAdd(&d_cA[b], 1u);
            }
            __syncthreads();                     // sPart reused next batch
        }
    } else if (bid < NA + NBB) {
        // ================= Stage B: cosine + quantize + hist + LUT ============
        const int sub = bid - NA;
        for (int b = 0; b < NB; ++b) {
            if (tid == 0) spin_ge(&d_cA[b], NA);
            __syncthreads();
            __threadfence();

            // a-hat (fixed-order combine of the two halves per plane)
            if (tid < NC)
                sA[tid] = (d_part[(b * NC + tid) * 2] +
                           d_part[(b * NC + tid) * 2 + 1]) * (1.0f / HW);
            sU[tid] = 0u;
            __syncthreads();
            sPart[tid] = (tid < NC) ? sA[tid] * sA[tid] : 0.f;
            __syncthreads();
            for (int o = 128; o > 0; o >>= 1) {
                if (tid < o) sPart[tid] += sPart[tid + o];
                __syncthreads();
            }
            const float inv = 1.0f / fmaxf(sqrtf(sPart[0]), 1e-12f);
            __syncthreads();
            if (tid < NC) sA[tid] *= inv;
            __syncthreads();

            // cosine for 128 float4-pixels, channels split across thread halves
            const int px = (sub << 7) + (tid & 127);
            const int c0 = (tid >> 7) << 5;
            const float4* fp = (const float4*)F + ((size_t)b << 20) + px;
            float d0 = 0.f, d1 = 0.f, d2 = 0.f, d3 = 0.f;
            float s0 = 0.f, s1 = 0.f, s2 = 0.f, s3 = 0.f;
            #pragma unroll 8
            for (int i = 0; i < 32; ++i) {
                float4 v = fp[(size_t)(c0 + i) << 14];
                float ac = sA[c0 + i];
                d0 += ac * v.x; d1 += ac * v.y; d2 += ac * v.z; d3 += ac * v.w;
                s0 += v.x * v.x; s1 += v.y * v.y; s2 += v.z * v.z; s3 += v.w * v.w;
            }
            sPart[0 * 256 + tid] = d0; sPart[1 * 256 + tid] = d1;
            sPart[2 * 256 + tid] = d2; sPart[3 * 256 + tid] = d3;
            sPart[4 * 256 + tid] = s0; sPart[5 * 256 + tid] = s1;
            sPart[6 * 256 + tid] = s2; sPart[7 * 256 + tid] = s3;
            __syncthreads();

            if (tid < 128) {
                float D0 = sPart[0 * 256 + tid] + sPart[0 * 256 + tid + 128];
                float D1 = sPart[1 * 256 + tid] + sPart[1 * 256 + tid + 128];
                float D2 = sPart[2 * 256 + tid] + sPart[2 * 256 + tid + 128];
                float D3 = sPart[3 * 256 + tid] + sPart[3 * 256 + tid + 128];
                float S0 = sPart[4 * 256 + tid] + sPart[4 * 256 + tid + 128];
                float S1 = sPart[5 * 256 + tid] + sPart[5 * 256 + tid + 128];
                float S2 = sPart[6 * 256 + tid] + sPart[6 * 256 + tid + 128];
                float S3 = sPart[7 * 256 + tid] + sPart[7 * 256 + tid + 128];
                int q0 = ((int)((D0 / fmaxf(sqrtf(S0), 1e-12f)) * 255.0f)) & 255;
                int q1 = ((int)((D1 / fmaxf(sqrtf(S1), 1e-12f)) * 255.0f)) & 255;
                int q2 = ((int)((D2 / fmaxf(sqrtf(S2), 1e-12f)) * 255.0f)) & 255;
                int q3 = ((int)((D3 / fmaxf(sqrtf(S3), 1e-12f)) * 255.0f)) & 255;
                atomicAdd(&sU[q0], 1u); atomicAdd(&sU[q1], 1u);
                atomicAdd(&sU[q2], 1u); atomicAdd(&sU[q3], 1u);
                const int mypx = (sub << 7) + tid;
                *(uchar4*)(d_q + ((size_t)b << 16) + ((size_t)mypx << 2)) =
                    make_uchar4((unsigned char)q0, (unsigned char)q1,
                                (unsigned char)q2, (unsigned char)q3);
            }
            __syncthreads();
            unsigned int cnt = sU[tid];
            if (cnt) atomicAdd(&d_hist[b * NBINS + tid], cnt);
            __syncthreads();

            if (tid == 0) {
                __threadfence();
                unsigned int old = atomicAdd(&d_cB[b], 1u);
                sLast = (old == NBB - 1);
            }
            __syncthreads();

            if (sLast) {                         // last B block builds the LUT
                __threadfence();
                float h = (float)d_hist[b * NBINS + tid];
                float* cdf = sPart;
                float* tmp = sPart + 256;
                cdf[tid] = h;
                __syncthreads();
                for (int o = 1; o < NBINS; o <<= 1) {
                    float v = cdf[tid];
                    float add = (tid >= o) ? cdf[tid - o] : 0.f;
                    __syncthreads();
                    cdf[tid] = v + add;
                    __syncthreads();
                }
                tmp[tid] = (h > 0.f) ? cdf[tid] : (float)(HW + 1);
                __syncthreads();
                for (int o = 128; o > 0; o >>= 1) {
                    if (tid < o) tmp[tid] = fminf(tmp[tid], tmp[tid + o]);
                    __syncthreads();
                }
                float cmin  = tmp[0];
                float denom = fmaxf((float)HW - cmin, 1.0f);
                float lut   = rintf((cdf[tid] - cmin) * (255.0f / denom));
                lut = fminf(fmaxf(lut, 0.0f), 255.0f);
                d_scale[b * NBINS + tid] = lut * (1.0f / 255.0f);
                __syncthreads();
                if (tid == 0) {
                    __threadfence();
                    atomicAdd(&d_cB[b], 1u);     // -> 129 : LUT ready
                }
            }
            __syncthreads();
        }
    } else {
        // ================= Stage C: out = F * scale[q] (L2 read + DRAM write) =
        const int sub = bid - NA - NBB;
        for (int b = 0; b < NB; ++b) {
            if (tid == 0) spin_ge(&d_cB[b], NBB + 1);
            __syncthreads();
            __threadfence();

            sA[tid] = d_scale[b * NBINS + tid];
            __syncthreads();

            const float4* Fb = (const float4*)F + ((size_t)b << 20);
            float4*       Ob = (float4*)out + ((size_t)b << 20);
            const int base = sub << 12;          // 4096 float4 per block
            #pragma unroll 4
            for (int k = 0; k < 16; ++k) {
                int idx = base + k * 256 + tid;
                int p4  = idx & 16383;
                uchar4 q = *(const uchar4*)(d_q + ((size_t)b << 16) +
                                            ((size_t)p4 << 2));
                float4 v = __ldcs(Fb + idx);     // last use: evict-first
                float4 o;
                o.x = v.x * sA[q.x];
                o.y = v.y * sA[q.y];
                o.z = v.z * sA[q.z];
                o.w = v.w * sA[q.w];
                __stcs(Ob + idx, o);             // streaming store
            }
            if (tid == 0) {
                __threadfence();
                atomicAdd(&d_cC[b], 1u);
            }
            __syncthreads();                     // sA reused next batch
        }
    }
}

// ============================================================
extern "C" void kernel_launch(void* const* d_in, const int* in_sizes, int n_in,
                              void* d_out, int out_size) {
    const float* F = (const float*)d_in[0];
    float* out = (float*)d_out;
    (void)in_sizes; (void)n_in; (void)out_size;

    k_init<<<NB, NBINS>>>();
    k_pipe<<<NBLK, 256>>>(F, out);
}